// round 12
// baseline (speedup 1.0000x reference)
#include <cuda_runtime.h>

// Problem constants (fixed shapes)
#define DIM   2048
#define NHEAD 16
#define HDIM  128
#define SEQ   2048
#define MROWS 4096   // BATCH * SEQ

// Scratch (allocation-free rule: __device__ globals)
__device__ float g_q[8388608];    // [B,H,S,HDIM]
__device__ float g_k[8388608];
__device__ float g_v[8388608];
__device__ float g_ctx[8388608];  // [B*S, DIM]

// ---------------------------------------------------------------------------
// NT SGEMM body: C[128x128] += A[M,K] * W[N,K]^T, BK=16, 256 threads,
// 8x8 per-thread microtile (split 4+4 with 64 offset for conflict-free smem).
// ---------------------------------------------------------------------------
__device__ __forceinline__ void gemm_body(
    const float* __restrict__ A, const float* __restrict__ W,
    float acc[8][8], int bm, int bn,
    float (*As)[132], float (*Bs)[132], int tid)
{
    const int tx = tid & 15;
    const int ty = tid >> 4;

    for (int k0 = 0; k0 < DIM; k0 += 16) {
#pragma unroll
        for (int p = 0; p < 2; p++) {
            int id = tid + p * 256;
            int r  = id >> 2;
            int c  = (id & 3) << 2;
            float4 a = *(const float4*)(A + (size_t)(bm + r) * DIM + k0 + c);
            As[c + 0][r] = a.x; As[c + 1][r] = a.y;
            As[c + 2][r] = a.z; As[c + 3][r] = a.w;
            float4 b = *(const float4*)(W + (size_t)(bn + r) * DIM + k0 + c);
            Bs[c + 0][r] = b.x; Bs[c + 1][r] = b.y;
            Bs[c + 2][r] = b.z; Bs[c + 3][r] = b.w;
        }
        __syncthreads();
#pragma unroll
        for (int kk = 0; kk < 16; kk++) {
            float av[8], bv[8];
            *(float4*)&av[0] = *(const float4*)&As[kk][ty * 4];
            *(float4*)&av[4] = *(const float4*)&As[kk][ty * 4 + 64];
            *(float4*)&bv[0] = *(const float4*)&Bs[kk][tx * 4];
            *(float4*)&bv[4] = *(const float4*)&Bs[kk][tx * 4 + 64];
#pragma unroll
            for (int i = 0; i < 8; i++) {
#pragma unroll
                for (int j = 0; j < 8; j++) {
                    acc[i][j] += av[i] * bv[j];
                }
            }
        }
        __syncthreads();
    }
}

// ---------------------------------------------------------------------------
// Fused QKV projection: Y = X @ W^T, epilogue writes head-major [B,H,S,HDIM].
// grid = (DIM/128, MROWS/128, 3)
// ---------------------------------------------------------------------------
__global__ __launch_bounds__(256, 2) void gemm_qkv_kernel(
    const float* __restrict__ X,
    const float* __restrict__ Wq, const float* __restrict__ Wk,
    const float* __restrict__ Wv)
{
    __shared__ __align__(16) float As[16][132];
    __shared__ __align__(16) float Bs[16][132];

    const int tid = threadIdx.x;
    const int bm  = blockIdx.y * 128;
    const int bn  = blockIdx.x * 128;

    const float* W = (blockIdx.z == 0) ? Wq : (blockIdx.z == 1) ? Wk : Wv;
    float*       O = (blockIdx.z == 0) ? g_q : (blockIdx.z == 1) ? g_k : g_v;

    float acc[8][8];
#pragma unroll
    for (int i = 0; i < 8; i++)
#pragma unroll
        for (int j = 0; j < 8; j++) acc[i][j] = 0.0f;

    gemm_body(X, W, acc, bm, bn, As, Bs, tid);

    const int tx = tid & 15;
    const int ty = tid >> 4;
    const int h  = bn >> 7;  // whole 128-wide tile = exactly one head

#pragma unroll
    for (int i = 0; i < 8; i++) {
        int m = bm + ty * 4 + ((i < 4) ? i : (64 + i - 4));
        int b = m >> 11;          // m / SEQ
        int s = m & 2047;         // m % SEQ
        size_t base = ((size_t)(b * NHEAD + h) * SEQ + s) * HDIM;
        float4 v0 = make_float4(acc[i][0], acc[i][1], acc[i][2], acc[i][3]);
        float4 v1 = make_float4(acc[i][4], acc[i][5], acc[i][6], acc[i][7]);
        *(float4*)(O + base + tx * 4)      = v0;
        *(float4*)(O + base + tx * 4 + 64) = v1;
    }
}

// ---------------------------------------------------------------------------
// Output projection: out = ctx @ Wo^T, plain row-major store.
// grid = (DIM/128, MROWS/128)
// ---------------------------------------------------------------------------
__global__ __launch_bounds__(256, 2) void gemm_out_kernel(
    const float* __restrict__ Wo, float* __restrict__ out)
{
    __shared__ __align__(16) float As[16][132];
    __shared__ __align__(16) float Bs[16][132];

    const int tid = threadIdx.x;
    const int bm  = blockIdx.y * 128;
    const int bn  = blockIdx.x * 128;

    float acc[8][8];
#pragma unroll
    for (int i = 0; i < 8; i++)
#pragma unroll
        for (int j = 0; j < 8; j++) acc[i][j] = 0.0f;

    gemm_body(g_ctx, Wo, acc, bm, bn, As, Bs, tid);

    const int tx = tid & 15;
    const int ty = tid >> 4;
#pragma unroll
    for (int i = 0; i < 8; i++) {
        int m = bm + ty * 4 + ((i < 4) ? i : (64 + i - 4));
        size_t base = (size_t)m * DIM + bn;
        float4 v0 = make_float4(acc[i][0], acc[i][1], acc[i][2], acc[i][3]);
        float4 v1 = make_float4(acc[i][4], acc[i][5], acc[i][6], acc[i][7]);
        *(float4*)(out + base + tx * 4)      = v0;
        *(float4*)(out + base + tx * 4 + 64) = v1;
    }
}

// ---------------------------------------------------------------------------
// Flash attention, fp32, BQ=64, BKV=64, online softmax, 256 threads.
// Q,K stored d-major (transposed, pad 65) in smem for outer-product S phase;
// V natural [kv][d]. Context written as [B*S, H*HDIM].
// ---------------------------------------------------------------------------
#define FSM_QT 0         // [128][65]
#define FSM_KT 8320      // [128][65]
#define FSM_VS 16640     // [64][128]
#define FSM_PS 24832     // [64][64]
#define FSM_MS 28928     // [64] running max
#define FSM_LS 28992     // [64] running sum
#define FSM_CS 29056     // [64] correction factor
#define FSM_TOT 29120    // floats -> 116480 bytes

__global__ __launch_bounds__(256, 1) void flash_kernel(const float* __restrict__ mask)
{
    extern __shared__ float sm[];
    float* Qt  = sm + FSM_QT;
    float* Kt  = sm + FSM_KT;
    float* Vs  = sm + FSM_VS;
    float* Ps  = sm + FSM_PS;
    float* m_s = sm + FSM_MS;
    float* l_s = sm + FSM_LS;
    float* c_s = sm + FSM_CS;

    const int tid = threadIdx.x;
    const int q0  = blockIdx.x * 64;
    const int bh  = blockIdx.y;                 // b*NHEAD + h
    const float* Qg = g_q + (size_t)bh * SEQ * HDIM;
    const float* Kg = g_k + (size_t)bh * SEQ * HDIM;
    const float* Vg = g_v + (size_t)bh * SEQ * HDIM;

    // Load Q tile (64x128), transposed to Qt[d][r]
#pragma unroll
    for (int p = 0; p < 8; p++) {
        int id = tid + p * 256;
        int r  = id >> 5;
        int d  = (id & 31) << 2;
        float4 v = *(const float4*)(Qg + (size_t)(q0 + r) * HDIM + d);
        Qt[(d + 0) * 65 + r] = v.x;
        Qt[(d + 1) * 65 + r] = v.y;
        Qt[(d + 2) * 65 + r] = v.z;
        Qt[(d + 3) * 65 + r] = v.w;
    }
    if (tid < 64) { m_s[tid] = -3.0e38f; l_s[tid] = 0.0f; }

    float acc[8][4];
#pragma unroll
    for (int i = 0; i < 8; i++)
#pragma unroll
        for (int j = 0; j < 4; j++) acc[i][j] = 0.0f;

    const int ar = (tid >> 4) << 2;   // S-phase rows ar..ar+3
    const int cc = (tid & 15) << 2;   // S-phase cols cc..cc+3
    const int pr = (tid >> 5) << 3;   // PV rows pr..pr+7
    const int pc = (tid & 31) << 2;   // PV cols pc..pc+3
    const float scale = 0.08838834764831845f;  // 1/sqrt(HDIM)

    for (int kv0 = 0; kv0 < SEQ; kv0 += 64) {
        // Load K tile transposed, V tile natural
#pragma unroll
        for (int p = 0; p < 8; p++) {
            int id = tid + p * 256;
            int r  = id >> 5;
            int d  = (id & 31) << 2;
            float4 kv = *(const float4*)(Kg + (size_t)(kv0 + r) * HDIM + d);
            Kt[(d + 0) * 65 + r] = kv.x;
            Kt[(d + 1) * 65 + r] = kv.y;
            Kt[(d + 2) * 65 + r] = kv.z;
            Kt[(d + 3) * 65 + r] = kv.w;
            float4 vv = *(const float4*)(Vg + (size_t)(kv0 + r) * HDIM + d);
            *(float4*)(Vs + r * 128 + d) = vv;
        }
        __syncthreads();

        // ---- S = Q K^T (4x4 per thread over 64x64 tile) ----
        float s[4][4];
#pragma unroll
        for (int i = 0; i < 4; i++)
#pragma unroll
            for (int j = 0; j < 4; j++) s[i][j] = 0.0f;

#pragma unroll 4
        for (int k = 0; k < 128; k++) {
            float a0 = Qt[k * 65 + ar + 0];
            float a1 = Qt[k * 65 + ar + 1];
            float a2 = Qt[k * 65 + ar + 2];
            float a3 = Qt[k * 65 + ar + 3];
            float b0 = Kt[k * 65 + cc + 0];
            float b1 = Kt[k * 65 + cc + 1];
            float b2 = Kt[k * 65 + cc + 2];
            float b3 = Kt[k * 65 + cc + 3];
            s[0][0] += a0 * b0; s[0][1] += a0 * b1; s[0][2] += a0 * b2; s[0][3] += a0 * b3;
            s[1][0] += a1 * b0; s[1][1] += a1 * b1; s[1][2] += a1 * b2; s[1][3] += a1 * b3;
            s[2][0] += a2 * b0; s[2][1] += a2 * b1; s[2][2] += a2 * b2; s[2][3] += a2 * b3;
            s[3][0] += a3 * b0; s[3][1] += a3 * b1; s[3][2] += a3 * b2; s[3][3] += a3 * b3;
        }

        // ---- scale + mask + online softmax ----
#pragma unroll
        for (int i = 0; i < 4; i++) {
            int row = ar + i;
            float4 mk = *(const float4*)(mask + (size_t)(q0 + row) * SEQ + kv0 + cc);
            float v0 = s[i][0] * scale + mk.x;
            float v1 = s[i][1] * scale + mk.y;
            float v2 = s[i][2] * scale + mk.z;
            float v3 = s[i][3] * scale + mk.w;
            float mx = fmaxf(fmaxf(v0, v1), fmaxf(v2, v3));
#pragma unroll
            for (int o = 8; o > 0; o >>= 1)
                mx = fmaxf(mx, __shfl_xor_sync(0xffffffffu, mx, o));
            float oldm = m_s[row];
            float nm   = fmaxf(oldm, mx);
            float e0 = __expf(v0 - nm);
            float e1 = __expf(v1 - nm);
            float e2 = __expf(v2 - nm);
            float e3 = __expf(v3 - nm);
            *(float4*)(Ps + row * 64 + cc) = make_float4(e0, e1, e2, e3);
            float sum = e0 + e1 + e2 + e3;
#pragma unroll
            for (int o = 8; o > 0; o >>= 1)
                sum += __shfl_xor_sync(0xffffffffu, sum, o);
            if ((tid & 15) == 0) {
                float corr = __expf(oldm - nm);
                c_s[row] = corr;
                l_s[row] = l_s[row] * corr + sum;
                m_s[row] = nm;
            }
        }
        __syncthreads();

        // ---- O = O*corr + P V (8x4 per thread over 64x128 tile) ----
#pragma unroll
        for (int i = 0; i < 8; i++) {
            float cf = c_s[pr + i];
#pragma unroll
            for (int j = 0; j < 4; j++) acc[i][j] *= cf;
        }
#pragma unroll 2
        for (int k = 0; k < 64; k++) {
            float4 vv = *(const float4*)(Vs + k * 128 + pc);
#pragma unroll
            for (int i = 0; i < 8; i++) {
                float a = Ps[(pr + i) * 64 + k];
                acc[i][0] += a * vv.x;
                acc[i][1] += a * vv.y;
                acc[i][2] += a * vv.z;
                acc[i][3] += a * vv.w;
            }
        }
        __syncthreads();
    }

    // ---- finalize: divide by row sum, write ctx[B*S, H*HDIM] ----
    const int b = bh >> 4;
    const int h = bh & 15;
#pragma unroll
    for (int i = 0; i < 8; i++) {
        float inv = 1.0f / l_s[pr + i];
        int srow  = q0 + pr + i;
        size_t o  = ((size_t)(b * SEQ + srow)) * DIM + h * HDIM + pc;
        float4 ov = make_float4(acc[i][0] * inv, acc[i][1] * inv,
                                acc[i][2] * inv, acc[i][3] * inv);
        *(float4*)(g_ctx + o) = ov;
    }
}

// ---------------------------------------------------------------------------
// Launch: QKV gemm -> flash attention -> output gemm (single default stream,
// graph-capturable; no allocations, no syncs).
// ---------------------------------------------------------------------------
extern "C" void kernel_launch(void* const* d_in, const int* in_sizes, int n_in,
                              void* d_out, int out_size)
{
    (void)in_sizes; (void)n_in; (void)out_size;
    const float* x    = (const float*)d_in[0];
    // d_in[1] = rotary_emb (unused by reference)
    const float* mask = (const float*)d_in[2];
    const float* Wq   = (const float*)d_in[3];
    const float* Wk   = (const float*)d_in[4];
    const float* Wv   = (const float*)d_in[5];
    const float* Wo   = (const float*)d_in[6];
    float* out = (float*)d_out;

    cudaFuncSetAttribute(flash_kernel, cudaFuncAttributeMaxDynamicSharedMemorySize,
                         FSM_TOT * (int)sizeof(float));

    dim3 gq(DIM / 128, MROWS / 128, 3);
    gemm_qkv_kernel<<<gq, 256>>>(x, Wq, Wk, Wv);

    dim3 gf(SEQ / 64, 32);
    flash_kernel<<<gf, 256, FSM_TOT * (int)sizeof(float)>>>(mask);

    dim3 go(DIM / 128, MROWS / 128);
    gemm_out_kernel<<<go, 256>>>(Wo, out);
}